// round 10
// baseline (speedup 1.0000x reference)
#include <cuda_runtime.h>

#define BB   256
#define TT   1024
#define SS   7
#define HH   64
#define LL   4
#define OO   3
#define UU   8          // timesteps per barrier epoch (2 sub-blocks of 4)
#define SUB  4
#define BETA 0.8f
#define TH   1.0f
#define NEPOCH (TT / UU)      // 128
#define ROWF   68             // padded spike row: half0 at byte 0, half1 at byte 144

// 32-element dot product: spike chunk (16B-aligned) x register weight row.
__device__ __forceinline__ float dot32(const float* __restrict__ sp,
                                       const float* __restrict__ wrow) {
    float a0 = 0.f, a1 = 0.f;
    #pragma unroll
    for (int i = 0; i < 8; i++) {
        float4 sv = *(const float4*)(sp + 4 * i);
        a0 = fmaf(sv.x, wrow[4 * i + 0], a0);
        a1 = fmaf(sv.y, wrow[4 * i + 1], a1);
        a0 = fmaf(sv.z, wrow[4 * i + 2], a0);
        a1 = fmaf(sv.w, wrow[4 * i + 3], a1);
    }
    return a0 + a1;
}

// One CTA per batch element, 544 threads, 2 CTAs/SM.
// tids 0..511: layer threads. l = tid>>7, q = tid&127, unit h = q>>1, half = q&1.
// Each thread holds HALF a weight row (32 regs), computes 32-FMA partials,
// combines with its lane-pair via shfl_xor(1). Both halves run the membrane
// chain redundantly; only half==0 stores.
// tids 512..517: output layer (3 outputs x 2 halves), rest of warp 16 idles.
// Pipeline over epochs of UU=8 timesteps (one __syncthreads per epoch, 132
// barriers), each epoch processed as two sub-blocks of 4 independent dots so
// the live accumulator array stays p[4] (regs <= 60 -> no spill, 2 CTAs/SM).
// Per-timestep math bit-identical to the 352us R9 kernel.
__global__ __launch_bounds__(544, 2)
void snn_u8_kernel(const float* __restrict__ x,
                   const float* __restrict__ hidden0,
                   const float* __restrict__ w1,
                   const float* __restrict__ b1,
                   const float* __restrict__ w_h,
                   const float* __restrict__ b_h,
                   const float* __restrict__ w_out,
                   const float* __restrict__ b_out,
                   float* __restrict__ out_outputs,   // [B,T,OO]
                   float* __restrict__ out_hidden,    // [B,T,LL,HH]
                   float* __restrict__ out_xcopy)     // [B,T,SS]
{
    const int b   = blockIdx.x;
    const int tid = threadIdx.x;

    __shared__ __align__(16) float spk[2][LL][UU][ROWF];

    // ---- copy this batch's x slice to the output buffer (coalesced float4) ----
    {
        const float4* xs4 = (const float4*)(x + (size_t)b * TT * SS);
        float4*       xo4 = (float4*)(out_xcopy + (size_t)b * TT * SS);
        const int n4 = TT * SS / 4;  // 1792
        for (int i = tid; i < n4; i += blockDim.x) xo4[i] = xs4[i];
    }

    const bool is_layer = (tid < LL * HH * 2);           // 512
    const bool is_out   = (tid >= 512) && (tid < 512 + 2 * OO);
    const int  l    = tid >> 7;
    const int  q    = tid & 127;
    const int  h    = q >> 1;
    const int  half = q & 1;

    float wrow[32];
    float bias = 0.0f;
    float m    = 0.0f;
    int   hoff = 0;

    if (is_layer) {
        m    = hidden0[(size_t)b * TT * LL * HH + (size_t)l * HH + h];
        hoff = h + ((h >= 32) ? 4 : 0);
        if (l == 0) {
            bias = b1[h];
            wrow[0] = w1[h * SS + half * 4 + 0];
            wrow[1] = w1[h * SS + half * 4 + 1];
            wrow[2] = w1[h * SS + half * 4 + 2];
            wrow[3] = half ? 0.0f : w1[h * SS + 3];
        } else {
            const float* row = w_h + ((size_t)(l - 1) * HH + h) * HH + half * 32;
            #pragma unroll
            for (int i = 0; i < 32; i++) wrow[i] = row[i];
            bias = b_h[(l - 1) * HH + h];
        }
    } else if (is_out) {
        const int oj = (tid - 512) >> 1;
        const int oh = (tid - 512) & 1;
        const float* row = w_out + (size_t)oj * HH + oh * 32;
        #pragma unroll
        for (int i = 0; i < 32; i++) wrow[i] = row[i];
        bias = b_out[oj];
    }

    __syncthreads();

    const float* xrow   = x + (size_t)b * TT * SS;
    float*       hidptr = out_hidden + (size_t)b * TT * LL * HH
                          + (is_layer ? (l * HH + h) : 0);
    float*       outptr = out_outputs + (size_t)b * TT * OO
                          + (is_out ? ((tid - 512) >> 1) : 0);

    int buf = 0;
    for (int e = 0; e < NEPOCH + LL; e++) {
        if (is_layer) {
            if (e >= l && e < l + NEPOCH) {
                #pragma unroll
                for (int sb = 0; sb < UU / SUB; sb++) {
                    float p[SUB];
                    if (l == 0) {
                        #pragma unroll
                        for (int k = 0; k < SUB; k++) {
                            const float* xr = xrow + (sb * SUB + k) * SS + half * 4;
                            float a = 0.f;
                            a = fmaf(xr[0], wrow[0], a);
                            a = fmaf(xr[1], wrow[1], a);
                            a = fmaf(xr[2], wrow[2], a);
                            if (!half) a = fmaf(xr[3], wrow[3], a);
                            p[k] = a;
                        }
                    } else {
                        #pragma unroll
                        for (int k = 0; k < SUB; k++)
                            p[k] = dot32(&spk[buf ^ 1][l - 1][sb * SUB + k][half * 36], wrow);
                    }
                    #pragma unroll
                    for (int k = 0; k < SUB; k++) {
                        const float tot = p[k] + __shfl_xor_sync(0xffffffffu, p[k], 1);
                        const float c   = bias + tot;
                        const float reset = (m > TH) ? TH : 0.0f;
                        const float m_new = fmaf(BETA, m, c) - reset;
                        m = m_new;
                        if (!half) {
                            spk[buf][l][sb * SUB + k][hoff] = (m_new > TH) ? 1.0f : 0.0f;
                            hidptr[(size_t)(sb * SUB + k) * (LL * HH)] = m_new;
                        }
                    }
                }
                xrow   += UU * SS;
                hidptr += (size_t)UU * LL * HH;
            }
        } else if (is_out) {
            if (e >= LL) {
                const int oh = (tid - 512) & 1;
                #pragma unroll
                for (int sb = 0; sb < UU / SUB; sb++) {
                    float p[SUB];
                    #pragma unroll
                    for (int k = 0; k < SUB; k++)
                        p[k] = dot32(&spk[buf ^ 1][LL - 1][sb * SUB + k][oh * 36], wrow);
                    #pragma unroll
                    for (int k = 0; k < SUB; k++) {
                        float tot = p[k] + __shfl_xor_sync(0x3fu, p[k], 1);
                        if (!oh) outptr[(sb * SUB + k) * OO] = bias + tot;
                    }
                }
                outptr += UU * OO;
            }
        }
        __syncthreads();
        buf ^= 1;
    }
}

extern "C" void kernel_launch(void* const* d_in, const int* in_sizes, int n_in,
                              void* d_out, int out_size) {
    // metadata order: x, hidden_states, prev_obs, w1, b1, w_h, b_h, w_out, b_out
    const float* x       = (const float*)d_in[0];
    const float* hidden0 = (const float*)d_in[1];
    // d_in[2] = prev_obs (unused by reference)
    const float* w1      = (const float*)d_in[3];
    const float* b1      = (const float*)d_in[4];
    const float* w_h     = (const float*)d_in[5];
    const float* b_h     = (const float*)d_in[6];
    const float* w_out   = (const float*)d_in[7];
    const float* b_out   = (const float*)d_in[8];

    float* out_outputs = (float*)d_out;                                  // B*T*OO
    float* out_hidden  = out_outputs + (size_t)BB * TT * OO;             // B*T*LL*HH
    float* out_xcopy   = out_hidden + (size_t)BB * TT * LL * HH;         // B*T*SS

    snn_u8_kernel<<<BB, 544>>>(x, hidden0, w1, b1, w_h, b_h, w_out, b_out,
                               out_outputs, out_hidden, out_xcopy);
}